// round 13
// baseline (speedup 1.0000x reference)
#include <cuda_runtime.h>
#include <cstdint>

// EPS_68771016344265: 2x2 tensor-network contraction, S=2, OUT=4
// out[b,h,w,o] = sum_{s0..s3} x_h[w][s0] x_h[w+1][s1] x_{h+1}[w][s2] x_{h+1}[w+1][s3]
//               * core[s0,s1,s2,s3,o]
// q(h) = x_h[w] (x) x_h[w+1];  d(h)_j = sum_i q(h)_i C[i][j][:];  out(h) = sum_j q(h+1)_j d(h)_j
//
// R12: input strip staged GMEM->SMEM with cp.async (zero register cost for MLP, one
// latency exposure per block), compute reads SMEM (29cyc LDS). o-dim split across thread
// pairs (even lane -> o{0,1}, odd -> o{2,3}); per-thread half-core = 16 f32x2 = 32 regs.

#define NB 128
#define NH 128
#define NW 128
#define HN 127
#define WN 127
#define TH 16
#define TW 66            // padded smem row width in float2 (65 used)

typedef unsigned long long u64;

__device__ __forceinline__ u64 f2mul(u64 a, u64 b) {
    u64 r; asm("mul.rn.f32x2 %0,%1,%2;" : "=l"(r) : "l"(a), "l"(b)); return r;
}
__device__ __forceinline__ u64 f2fma(u64 a, u64 b, u64 c) {
    u64 r; asm("fma.rn.f32x2 %0,%1,%2,%3;" : "=l"(r) : "l"(a), "l"(b), "l"(c)); return r;
}
__device__ __forceinline__ u64 fdup(float x) {
    u64 r; asm("mov.b64 %0,{%1,%1};" : "=l"(r) : "f"(x)); return r;
}
__device__ __forceinline__ float2 f2unpack(u64 a) {
    float2 v; asm("mov.b64 {%0,%1},%2;" : "=f"(v.x), "=f"(v.y) : "l"(a)); return v;
}

template <int NROWS>   // pixel rows in this strip; reads smem rows 0..NROWS
__device__ __forceinline__ void compute_strip(const float2* __restrict__ tile,  // smem
                                              const u64* __restrict__ c,
                                              float2* __restrict__ outp,
                                              int slot, bool st)
{
    // row 0
    float2 xa = tile[slot];
    float2 xb = tile[slot + 1];
    u64 q0 = fdup(xa.x * xb.x);
    u64 q1 = fdup(xa.x * xb.y);
    u64 q2 = fdup(xa.y * xb.x);
    u64 q3 = fdup(xa.y * xb.y);

    u64 d[4];
    #pragma unroll
    for (int j = 0; j < 4; j++)
        d[j] = f2fma(q3, c[12+j], f2fma(q2, c[8+j], f2fma(q1, c[4+j], f2mul(q0, c[j]))));

    #pragma unroll
    for (int k = 1; k <= NROWS; ++k) {
        float2 ya = tile[k * TW + slot];       // LDS, immediate offsets
        float2 yb = tile[k * TW + slot + 1];
        u64 p0 = fdup(ya.x * yb.x);
        u64 p1 = fdup(ya.x * yb.y);
        u64 p2 = fdup(ya.y * yb.x);
        u64 p3 = fdup(ya.y * yb.y);

        // pixel row k-1: this thread's o-pair = sum_j p_j * d_j
        u64 o2 = f2fma(p3, d[3], f2fma(p2, d[2], f2fma(p1, d[1], f2mul(p0, d[0]))));
        if (st) outp[(k - 1) * 2 * WN] = f2unpack(o2);

        if (k < NROWS) {                        // d for next pixel (dead on last row)
            #pragma unroll
            for (int j = 0; j < 4; j++)
                d[j] = f2fma(p3, c[12+j], f2fma(p2, c[8+j], f2fma(p1, c[4+j], f2mul(p0, c[j]))));
        }
    }
}

__global__ __launch_bounds__(128, 8)
void eps_kernel(const float* __restrict__ in,
                const float* __restrict__ core,
                float2* __restrict__ out)
{
    __shared__ float2 tile[17 * TW];            // 8976 B

    const int tid  = threadIdx.x;
    const int slot = tid >> 1;
    const int op   = tid & 1;                   // which o-pair this thread owns
    const int w0   = blockIdx.y * 64;
    const int w    = w0 + slot;                 // 0..127
    const int b    = blockIdx.z;
    const int h0   = blockIdx.x * TH;

    // ---- stage input strip: rows h0..h0+nin-1, cols w0..w0+64 (clamped) ----
    const int nin = (blockIdx.x < 7) ? (TH + 1) : TH;          // strip 7: rows 112..127
    const float2* gsrc = reinterpret_cast<const float2*>(in) + (b * NH + h0) * NW + w0;

    for (int idx = tid; idx < nin * 65; idx += 128) {
        int row = idx / 65;
        int col = idx - row * 65;
        if (w0 + col < NW) {
            uint32_t s = (uint32_t)__cvta_generic_to_shared(&tile[row * TW + col]);
            const float2* g = gsrc + row * NW + col;
            asm volatile("cp.async.ca.shared.global [%0], [%1], 8;" :: "r"(s), "l"(g));
        }
    }
    asm volatile("cp.async.commit_group;" ::: "memory");

    // ---- core into registers while the copy is in flight ----
    u64 c[16];
    {
        const u64* cp = reinterpret_cast<const u64*>(core);
        #pragma unroll
        for (int k = 0; k < 16; k++) c[k] = cp[2 * k + op];
    }

    asm volatile("cp.async.wait_group 0;" ::: "memory");
    __syncthreads();

    float2* outp = out + ((b * HN + h0) * WN + w) * 2 + op;
    const bool st = (w < WN);

    if (blockIdx.x < 7) {
        compute_strip<TH>(tile, c, outp, slot, st);            // 16 pixel rows
    } else {
        compute_strip<HN - 7 * TH>(tile, c, outp, slot, st);   // 15 pixel rows
    }
}

extern "C" void kernel_launch(void* const* d_in, const int* in_sizes, int n_in,
                              void* d_out, int out_size)
{
    const float* in   = (const float*)d_in[0];   // (1,128,128,128,2) f32
    const float* core = (const float*)d_in[1];   // (2,2,2,2,4) f32
    float2* out = (float2*)d_out;                // (128,127,127,4) f32 viewed as float2

    dim3 grid((HN + TH - 1) / TH, 2, NB);        // (8, 2, 128) = 2048 blocks
    eps_kernel<<<grid, 128>>>(in, core, out);
}

// round 15
// speedup vs baseline: 1.0194x; 1.0194x over previous
#include <cuda_runtime.h>
#include <cstdint>

// EPS_68771016344265: 2x2 tensor-network contraction, S=2, OUT=4
// out[b,h,w,o] = sum_{s0..s3} x_h[w][s0] x_h[w+1][s1] x_{h+1}[w][s2] x_{h+1}[w+1][s3]
//               * core[s0,s1,s2,s3,o]
// q(h) = x_h[w] (x) x_h[w+1];  d(h)_j = sum_i q(h)_i C[i][j][:];  out(h) = sum_j q(h+1)_j d(h)_j
//
// R14: TH=32 strips; all input staged with 16B cp.async in TWO commit groups
// (rows 0..16 / 17..32) -> wait_group 1, compute half A (overlapping group-1 landing),
// wait_group 0, compute half B. o-dim split across thread pairs; per-thread half-core
// = 16 f32x2 = 32 regs (register resident).

#define NB 128
#define NH 128
#define NW 128
#define HN 127
#define WN 127
#define TH 32
#define TW 66            // padded smem row width in float2 (65 used; 528B, 16B-aligned)

typedef unsigned long long u64;

__device__ __forceinline__ u64 f2mul(u64 a, u64 b) {
    u64 r; asm("mul.rn.f32x2 %0,%1,%2;" : "=l"(r) : "l"(a), "l"(b)); return r;
}
__device__ __forceinline__ u64 f2fma(u64 a, u64 b, u64 c) {
    u64 r; asm("fma.rn.f32x2 %0,%1,%2,%3;" : "=l"(r) : "l"(a), "l"(b), "l"(c)); return r;
}
__device__ __forceinline__ u64 fdup(float x) {
    u64 r; asm("mov.b64 %0,{%1,%1};" : "=l"(r) : "f"(x)); return r;
}
__device__ __forceinline__ float2 f2unpack(u64 a) {
    float2 v; asm("mov.b64 {%0,%1},%2;" : "=f"(v.x), "=f"(v.y) : "l"(a)); return v;
}

// Compute NPX pixel rows from smem rows [0..NPX] of `tile` (already offset to phase base).
template <int NPX>
__device__ __forceinline__ void compute_half(const float2* __restrict__ tile,
                                             const u64* __restrict__ c,
                                             float2* __restrict__ outp,
                                             int slot, bool st)
{
    float2 xa = tile[slot];
    float2 xb = tile[slot + 1];
    u64 q0 = fdup(xa.x * xb.x);
    u64 q1 = fdup(xa.x * xb.y);
    u64 q2 = fdup(xa.y * xb.x);
    u64 q3 = fdup(xa.y * xb.y);

    u64 d[4];
    #pragma unroll
    for (int j = 0; j < 4; j++)
        d[j] = f2fma(q3, c[12+j], f2fma(q2, c[8+j], f2fma(q1, c[4+j], f2mul(q0, c[j]))));

    #pragma unroll
    for (int k = 1; k <= NPX; ++k) {
        float2 ya = tile[k * TW + slot];
        float2 yb = tile[k * TW + slot + 1];
        u64 p0 = fdup(ya.x * yb.x);
        u64 p1 = fdup(ya.x * yb.y);
        u64 p2 = fdup(ya.y * yb.x);
        u64 p3 = fdup(ya.y * yb.y);

        u64 o2 = f2fma(p3, d[3], f2fma(p2, d[2], f2fma(p1, d[1], f2mul(p0, d[0]))));
        if (st) outp[(k - 1) * 2 * WN] = f2unpack(o2);

        if (k < NPX) {
            #pragma unroll
            for (int j = 0; j < 4; j++)
                d[j] = f2fma(p3, c[12+j], f2fma(p2, c[8+j], f2fma(p1, c[4+j], f2mul(p0, c[j]))));
        }
    }
}

// Stage smem rows [r0, r1) of the block's strip with 16B cp.async (plus 8B tail col).
__device__ __forceinline__ void stage_rows(float2* __restrict__ tile,
                                           const float2* __restrict__ gsrc,  // strip row 0, col w0
                                           int r0, int r1, int tid, bool tailcol)
{
    const int n = (r1 - r0) * 33;
    for (int idx = tid; idx < n; idx += 128) {
        int row = r0 + idx / 33;
        int q   = idx % 33;
        if (q < 32) {
            uint32_t s = (uint32_t)__cvta_generic_to_shared(&tile[row * TW + q * 2]);
            const float2* g = gsrc + row * NW + q * 2;
            asm volatile("cp.async.ca.shared.global [%0], [%1], 16;" :: "r"(s), "l"(g));
        } else if (tailcol) {
            uint32_t s = (uint32_t)__cvta_generic_to_shared(&tile[row * TW + 64]);
            const float2* g = gsrc + row * NW + 64;
            asm volatile("cp.async.ca.shared.global [%0], [%1], 8;" :: "r"(s), "l"(g));
        }
    }
}

__global__ __launch_bounds__(128, 8)
void eps_kernel(const float* __restrict__ in,
                const float* __restrict__ core,
                float2* __restrict__ out)
{
    __shared__ float2 tile[(TH + 1) * TW];       // 33*66*8 = 17,424 B

    const int tid  = threadIdx.x;
    const int slot = tid >> 1;
    const int op   = tid & 1;
    const int w0   = blockIdx.y * 64;
    const int w    = w0 + slot;                  // 0..127
    const int b    = blockIdx.z;
    const int h0   = blockIdx.x * TH;

    const bool last = (blockIdx.x == 3);         // h0=96: input rows 96..127 (32), 31 px rows
    const int  nin  = last ? TH : (TH + 1);      // smem rows staged
    const bool tailcol = (w0 == 0);              // col 64 exists only for the w0=0 half

    const float2* gsrc = reinterpret_cast<const float2*>(in) + (b * NH + h0) * NW + w0;

    // Phase A rows [0,17), phase B rows [17,nin) — both issued before any wait.
    stage_rows(tile, gsrc, 0, 17, tid, tailcol);
    asm volatile("cp.async.commit_group;" ::: "memory");
    stage_rows(tile, gsrc, 17, nin, tid, tailcol);
    asm volatile("cp.async.commit_group;" ::: "memory");

    // Core into registers while copies are in flight.
    u64 c[16];
    {
        const u64* cp = reinterpret_cast<const u64*>(core);
        #pragma unroll
        for (int k = 0; k < 16; k++) c[k] = cp[2 * k + op];
    }

    float2* outp = out + ((b * HN + h0) * WN + w) * 2 + op;
    const bool st = (w < WN);

    asm volatile("cp.async.wait_group 1;" ::: "memory");
    __syncthreads();

    // Half A: pixel rows h0..h0+15 (smem rows 0..16)
    compute_half<16>(tile, c, outp, slot, st);

    asm volatile("cp.async.wait_group 0;" ::: "memory");
    __syncthreads();

    // Half B: pixel rows h0+16.. (smem rows 16..nin-1)
    if (!last) {
        compute_half<16>(tile + 16 * TW, c, outp + 16 * 2 * WN, slot, st);
    } else {
        compute_half<15>(tile + 16 * TW, c, outp + 16 * 2 * WN, slot, st);
    }
}

extern "C" void kernel_launch(void* const* d_in, const int* in_sizes, int n_in,
                              void* d_out, int out_size)
{
    const float* in   = (const float*)d_in[0];   // (1,128,128,128,2) f32
    const float* core = (const float*)d_in[1];   // (2,2,2,2,4) f32
    float2* out = (float2*)d_out;                // (128,127,127,4) f32 viewed as float2

    dim3 grid((HN + TH - 1) / TH, 2, NB);        // (4, 2, 128) = 1024 blocks
    eps_kernel<<<grid, 128>>>(in, core, out);
}

// round 17
// speedup vs baseline: 1.1859x; 1.1633x over previous
#include <cuda_runtime.h>

// EPS_68771016344265: 2x2 tensor-network contraction, S=2, OUT=4
// out[b,h,w,o] = sum_{s0..s3} x_h[w][s0] x_h[w+1][s1] x_{h+1}[w][s2] x_{h+1}[w+1][s3]
//               * core[s0,s1,s2,s3,o]
// q(h) = x_h[w] (x) x_h[w+1];  d(h)_j = sum_i q(h)_i C[i][j][:];  out(h) = sum_j q(h+1)_j d(h)_j
//
// R16: warm-L2 regime. Direct LDG with compile-time-unrolled TH=8 strips (grid 4096 ->
// fine wave quantization), o-dim split across thread pairs (per-thread half-core =
// 16 f32x2 = 32 regs), 64-reg cap -> 8 blocks/SM resident (32 warps). No barriers,
// no staging: cross-warp occupancy covers the ~240cyc L2 latency.

#define NB 128
#define NH 128
#define NW 128
#define HN 127
#define WN 127
#define TH 8

typedef unsigned long long u64;

__device__ __forceinline__ u64 f2mul(u64 a, u64 b) {
    u64 r; asm("mul.rn.f32x2 %0,%1,%2;" : "=l"(r) : "l"(a), "l"(b)); return r;
}
__device__ __forceinline__ u64 f2fma(u64 a, u64 b, u64 c) {
    u64 r; asm("fma.rn.f32x2 %0,%1,%2,%3;" : "=l"(r) : "l"(a), "l"(b), "l"(c)); return r;
}
__device__ __forceinline__ u64 fdup(float x) {
    u64 r; asm("mov.b64 %0,{%1,%1};" : "=l"(r) : "f"(x)); return r;
}
__device__ __forceinline__ float2 f2unpack(u64 a) {
    float2 v; asm("mov.b64 {%0,%1},%2;" : "=f"(v.x), "=f"(v.y) : "l"(a)); return v;
}

template <int NROWS>   // pixel rows in this strip; input rows = NROWS+1, all offsets immediate
__device__ __forceinline__ void run_strip(const float2* __restrict__ ip,   // strip row 0, col w
                                          const float2* __restrict__ ipn,  // strip row 0, col w+1
                                          const u64* __restrict__ c,
                                          float2* __restrict__ outp,       // pixel (h0,w), o-slot
                                          bool st)
{
    // row 0
    float2 xa = ip[0];
    float2 xb = ipn[0];
    u64 q0 = fdup(xa.x * xb.x);
    u64 q1 = fdup(xa.x * xb.y);
    u64 q2 = fdup(xa.y * xb.x);
    u64 q3 = fdup(xa.y * xb.y);

    u64 d[4];
    #pragma unroll
    for (int j = 0; j < 4; j++)
        d[j] = f2fma(q3, c[12+j], f2fma(q2, c[8+j], f2fma(q1, c[4+j], f2mul(q0, c[j]))));

    #pragma unroll
    for (int k = 1; k <= NROWS; ++k) {
        float2 ya = ip[k * NW];          // LDG [base + imm]
        float2 yb = ipn[k * NW];
        u64 p0 = fdup(ya.x * yb.x);
        u64 p1 = fdup(ya.x * yb.y);
        u64 p2 = fdup(ya.y * yb.x);
        u64 p3 = fdup(ya.y * yb.y);

        // pixel row k-1: this thread's o-pair = sum_j p_j * d_j
        u64 o2 = f2fma(p3, d[3], f2fma(p2, d[2], f2fma(p1, d[1], f2mul(p0, d[0]))));
        if (st) outp[(k - 1) * 2 * WN] = f2unpack(o2);

        if (k < NROWS) {                 // d for next pixel (dead on last row)
            #pragma unroll
            for (int j = 0; j < 4; j++)
                d[j] = f2fma(p3, c[12+j], f2fma(p2, c[8+j], f2fma(p1, c[4+j], f2mul(p0, c[j]))));
        }
    }
}

__global__ __launch_bounds__(128, 8)
void eps_kernel(const float* __restrict__ in,
                const float* __restrict__ core,
                float2* __restrict__ out)
{
    const int lane = threadIdx.x;
    const int slot = lane >> 1;
    const int op   = lane & 1;                       // which o-pair this thread owns
    const int w    = blockIdx.y * 64 + slot;         // 0..127
    const int b    = blockIdx.z;
    const int h0   = blockIdx.x * TH;

    // Per-thread half-core: c[k] = {core[k][2*op], core[k][2*op+1]}
    u64 c[16];
    {
        const u64* cp = reinterpret_cast<const u64*>(core);
        #pragma unroll
        for (int k = 0; k < 16; k++) c[k] = cp[2 * k + op];
    }

    const int wp1 = (w < NW - 1) ? (w + 1) : w;      // clamp; w=127 never stores
    const float2* base = reinterpret_cast<const float2*>(in) + (b * NH + h0) * NW;
    const float2* ip  = base + w;
    const float2* ipn = base + wp1;
    float2* outp = out + ((b * HN + h0) * WN + w) * 2 + op;
    const bool st = (w < WN);

    if (blockIdx.x < 15) {
        run_strip<TH>(ip, ipn, c, outp, st);             // strips 0..14: 8 pixel rows
    } else {
        run_strip<HN - 15 * TH>(ip, ipn, c, outp, st);   // strip 15: 7 pixel rows (120..126)
    }
}

extern "C" void kernel_launch(void* const* d_in, const int* in_sizes, int n_in,
                              void* d_out, int out_size)
{
    const float* in   = (const float*)d_in[0];   // (1,128,128,128,2) f32
    const float* core = (const float*)d_in[1];   // (2,2,2,2,4) f32
    float2* out = (float2*)d_out;                // (128,127,127,4) f32 viewed as float2

    dim3 grid((HN + TH - 1) / TH, 2, NB);        // (16, 2, 128) = 4096 blocks
    eps_kernel<<<grid, 128>>>(in, core, out);
}